// round 6
// baseline (speedup 1.0000x reference)
#include <cuda_runtime.h>
#include <cuda_fp16.h>
#include <cstdint>

#define D_DIM 512
#define B_MAX 2048
#define T_CAP 64

// ---------------- device scratch ----------------
__device__ __half g_wfh[3 * D_DIM * D_DIM];
__device__ __half g_wsh[3 * D_DIM * D_DIM];
__device__ __half g_wgh[D_DIM * 2 * D_DIM];
__device__ float  g_gif[T_CAP * 3 * D_DIM];
__device__ float  g_gis[T_CAP * 3 * D_DIM];
__device__ float  g_zf  [B_MAX * D_DIM];
__device__ __half g_zfh [B_MAX * D_DIM];
__device__ float  g_zfn [B_MAX * D_DIM];
__device__ __half g_zfnh[B_MAX * D_DIM];
__device__ float  g_zs0 [B_MAX * D_DIM];
__device__ __half g_zs0h[B_MAX * D_DIM];
__device__ float  g_zs1 [B_MAX * D_DIM];
__device__ __half g_zs1h[B_MAX * D_DIM];
__device__ float  g_ghf[B_MAX * 3 * D_DIM];
__device__ float  g_ghs[B_MAX * 3 * D_DIM];
__device__ float  g_gpre[B_MAX * D_DIM];
__device__ unsigned long long g_bar;

// ---------------- helpers ----------------
__device__ __forceinline__ float sigm(float x) { return 1.0f / (1.0f + __expf(-x)); }

__device__ __forceinline__ void mma16(float* c, const uint32_t* a, uint32_t b0, uint32_t b1) {
    asm volatile(
        "mma.sync.aligned.m16n8k16.row.col.f32.f16.f16.f32 "
        "{%0,%1,%2,%3}, {%4,%5,%6,%7}, {%8,%9}, {%0,%1,%2,%3};\n"
        : "+f"(c[0]), "+f"(c[1]), "+f"(c[2]), "+f"(c[3])
        : "r"(a[0]), "r"(a[1]), "r"(a[2]), "r"(a[3]), "r"(b0), "r"(b1));
}

__device__ __forceinline__ void cp16(void* s, const void* g) {
    uint32_t sa = (uint32_t)__cvta_generic_to_shared(s);
    asm volatile("cp.async.cg.shared.global [%0], [%1], 16;\n" :: "r"(sa), "l"(g));
}

// grid-wide barrier: all CTAs resident (single wave) by construction.
__device__ __forceinline__ void gsync(unsigned long long& target) {
    __syncthreads();
    target += gridDim.x;
    if (threadIdx.x == 0) {
        __threadfence();
        atomicAdd(&g_bar, 1ULL);
        unsigned long long v;
        while (true) {
            asm volatile("ld.acquire.gpu.u64 %0, [%1];" : "=l"(v) : "l"(&g_bar) : "memory");
            if (v >= target) break;
            __nanosleep(32);
        }
    }
    __syncthreads();
}

// ---------------- CTA-wide fp16 GEMM tile: C[tile] = A @ W^T ----------------
#define KC  64
#define SSTRH 72
#define SMEM_HALVES ((2 * 128 + 2 * 128) * SSTRH)     // 36864 halves = 73728 B

template<int TM_>
__device__ __forceinline__ void gemm_tile(
    __half* hsm,
    const __half* __restrict__ A0, const __half* __restrict__ A1, int splitK, int lda,
    const __half* __restrict__ W, int ldw, float* __restrict__ C, int ldc, int K,
    int rowBase, int colBase)
{
    constexpr int A_STAGE = TM_ * SSTRH;
    constexpr int B_STAGE = 128 * SSTRH;
    __half* As = hsm;
    __half* Bs = hsm + 2 * A_STAGE;

    const int tid  = threadIdx.x;
    const int warp = tid >> 5, lane = tid & 31;
    constexpr int MW = (TM_ == 128) ? 4 : 2;
    constexpr int NJ = (TM_ == 128) ? 8 : 4;
    const int wm0 = (warp % MW) * 32;
    const int wn0 = (warp / MW) * (NJ * 8);
    const int group = lane >> 2, tid4 = lane & 3;

    float acc[2][NJ][4];
#pragma unroll
    for (int i = 0; i < 2; i++)
#pragma unroll
        for (int j = 0; j < NJ; j++)
#pragma unroll
            for (int k = 0; k < 4; k++) acc[i][j][k] = 0.0f;

    auto issue = [&](int ic, int buf) {
        const int kk = ic * KC;
        const __half* Ab; int kloc;
        if (kk < splitK) { Ab = A0; kloc = kk; }
        else             { Ab = A1; kloc = kk - splitK; }
        __half* as = As + buf * A_STAGE;
        __half* bs = Bs + buf * B_STAGE;
#pragma unroll
        for (int t = 0; t < TM_ / 32; t++) {
            const int seg = tid + t * 256;
            const int r = seg >> 3, c = (seg & 7) * 8;
            cp16(as + r * SSTRH + c, Ab + (size_t)(rowBase + r) * lda + kloc + c);
        }
#pragma unroll
        for (int t = 0; t < 4; t++) {
            const int seg = tid + t * 256;
            const int r = seg >> 3, c = (seg & 7) * 8;
            cp16(bs + r * SSTRH + c, W + (size_t)(colBase + r) * ldw + kk + c);
        }
        asm volatile("cp.async.commit_group;\n" ::);
    };

    const int NK = K / KC;
    issue(0, 0);

    for (int ic = 0; ic < NK; ic++) {
        const int buf = ic & 1;
        if (ic + 1 < NK) {
            issue(ic + 1, buf ^ 1);
            asm volatile("cp.async.wait_group 1;\n" ::);
        } else {
            asm volatile("cp.async.wait_group 0;\n" ::);
        }
        __syncthreads();

        const __half* as = As + buf * A_STAGE;
        const __half* bs = Bs + buf * B_STAGE;
#pragma unroll
        for (int k16 = 0; k16 < KC / 16; k16++) {
            const int k0 = k16 * 16;
            uint32_t a[2][4];
#pragma unroll
            for (int i = 0; i < 2; i++) {
                const int r = wm0 + i * 16 + group;
                a[i][0] = *(const uint32_t*)&as[ r      * SSTRH + k0 + 2 * tid4    ];
                a[i][1] = *(const uint32_t*)&as[(r + 8) * SSTRH + k0 + 2 * tid4    ];
                a[i][2] = *(const uint32_t*)&as[ r      * SSTRH + k0 + 2 * tid4 + 8];
                a[i][3] = *(const uint32_t*)&as[(r + 8) * SSTRH + k0 + 2 * tid4 + 8];
            }
#pragma unroll
            for (int j = 0; j < NJ; j++) {
                const int n = wn0 + j * 8 + group;
                uint32_t b0 = *(const uint32_t*)&bs[n * SSTRH + k0 + 2 * tid4    ];
                uint32_t b1 = *(const uint32_t*)&bs[n * SSTRH + k0 + 2 * tid4 + 8];
                mma16(acc[0][j], a[0], b0, b1);
                mma16(acc[1][j], a[1], b0, b1);
            }
        }
        __syncthreads();
    }

#pragma unroll
    for (int i = 0; i < 2; i++) {
        const int r0 = rowBase + wm0 + i * 16 + group;
#pragma unroll
        for (int j = 0; j < NJ; j++) {
            const int c0 = colBase + wn0 + j * 8 + tid4 * 2;
            *(float2*)&C[(size_t)r0 * ldc + c0]       = make_float2(acc[i][j][0], acc[i][j][1]);
            *(float2*)&C[(size_t)(r0 + 8) * ldc + c0] = make_float2(acc[i][j][2], acc[i][j][3]);
        }
    }
}

// ---------------- GRU elementwise (one float4 vector) ----------------
__device__ __forceinline__ void gru_vec(
    const float* __restrict__ gh, const float* __restrict__ gi,
    const float* __restrict__ bhh, const float* __restrict__ h,
    float* __restrict__ ho, __half* __restrict__ hoh, int i)
{
    const int b = i >> 9;
    const int j = i & (D_DIM - 1);
    const size_t base = (size_t)b * (3 * D_DIM) + j;

    float4 gA = *(const float4*)(gh + base);
    float4 gB = *(const float4*)(gh + base + D_DIM);
    float4 gC = *(const float4*)(gh + base + 2 * D_DIM);
    float4 iA = *(const float4*)(gi + j);
    float4 iB = *(const float4*)(gi + j + D_DIM);
    float4 iC = *(const float4*)(gi + j + 2 * D_DIM);
    float4 bA = *(const float4*)(bhh + j);
    float4 bB = *(const float4*)(bhh + j + D_DIM);
    float4 bC = *(const float4*)(bhh + j + 2 * D_DIM);
    float4 hv = *(const float4*)(h + i);

    float4 o;
    { float r = sigm(iA.x + gA.x + bA.x); float z = sigm(iB.x + gB.x + bB.x);
      float n = tanhf(iC.x + r * (gC.x + bC.x)); o.x = n + z * (hv.x - n); }
    { float r = sigm(iA.y + gA.y + bA.y); float z = sigm(iB.y + gB.y + bB.y);
      float n = tanhf(iC.y + r * (gC.y + bC.y)); o.y = n + z * (hv.y - n); }
    { float r = sigm(iA.z + gA.z + bA.z); float z = sigm(iB.z + gB.z + bB.z);
      float n = tanhf(iC.z + r * (gC.z + bC.z)); o.z = n + z * (hv.z - n); }
    { float r = sigm(iA.w + gA.w + bA.w); float z = sigm(iB.w + gB.w + bB.w);
      float n = tanhf(iC.w + r * (gC.w + bC.w)); o.w = n + z * (hv.w - n); }

    *(float4*)(ho + i) = o;
    *(__half2*)(hoh + i)     = make_half2(__float2half_rn(o.x), __float2half_rn(o.y));
    *(__half2*)(hoh + i + 2) = make_half2(__float2half_rn(o.z), __float2half_rn(o.w));
}

// ---------------- fused persistent scan kernel ----------------
__global__ __launch_bounds__(256, 2) void fused_scan(
    const float* __restrict__ fbhh, const float* __restrict__ sbhh,
    const float* __restrict__ gateb,
    const float* __restrict__ gamma, const float* __restrict__ beta,
    float* __restrict__ out, int B, int T)
{
    extern __shared__ __half hsm[];
    const int tid = threadIdx.x;
    const int BD = B * D_DIM;
    const int vecBD = BD / 4;
    const int MT = B / 128;          // fast-GEMM row tiles (16)
    const int FTILES = MT * 12;      // fast tiles per step (192)
    unsigned long long target = 0;

    float*  zs[2]  = { g_zs0,  g_zs1 };
    __half* zsh[2] = { g_zs0h, g_zs1h };

    int cur = 0;
    for (int t = 0; t < T; t++) {
        const bool even = ((t & 1) == 0);

        // ---------- phase 1: hidden GEMMs (fast + split slow) ----------
        int nextra, sbase;
        if (t == 0)        { nextra = FTILES;     sbase = 0; }
        else if (!even)    { nextra = (t + 1 < T) ? FTILES / 2 : 0; sbase = 0; }
        else               { nextra = FTILES / 2; sbase = FTILES / 2; }

        const int ntile = FTILES + nextra;
        for (int w = blockIdx.x; w < ntile; w += gridDim.x) {
            if (w < FTILES) {
                const int r = w % MT, c = w / MT;
                gemm_tile<128>(hsm, g_zfh, g_zfh, 1 << 30, D_DIM,
                               g_wfh, D_DIM, g_ghf, 3 * D_DIM, D_DIM,
                               r * 128, c * 128);
            } else {
                const int idx = w - FTILES + sbase;
                const int r = idx % MT, c = idx / MT;
                gemm_tile<128>(hsm, zsh[cur], zsh[cur], 1 << 30, D_DIM,
                               g_wsh, D_DIM, g_ghs, 3 * D_DIM, D_DIM,
                               r * 128, c * 128);
            }
        }
        gsync(target);

        // ---------- phase 2: GRU elementwise ----------
        const int ncur = even ? (cur ^ 1) : cur;
        const float* gif_t = g_gif + (size_t)t * 3 * D_DIM;
        const float* gis_t = g_gis + (size_t)t * 3 * D_DIM;
        {
            const int tot = even ? 2 * vecBD : vecBD;
            for (int v = blockIdx.x * 256 + tid; v < tot; v += gridDim.x * 256) {
                if (v < vecBD) {
                    gru_vec(g_ghf, gif_t, fbhh, g_zf, g_zfn, g_zfnh, v * 4);
                } else {
                    const int i = (v - vecBD) * 4;
                    gru_vec(g_ghs, gis_t, sbhh, zs[cur], zs[ncur], zsh[ncur], i);
                }
            }
        }
        gsync(target);

        // ---------- phase 3: gate GEMM (concat via split-A), 64x128 tiles ----------
        {
            const int GT = B / 64;   // 32 row tiles x 4 col tiles
            for (int w = blockIdx.x; w < GT * 4; w += gridDim.x) {
                const int r = w % GT, c = w / GT;
                gemm_tile<64>(hsm, g_zfnh, zsh[ncur], D_DIM, D_DIM,
                              g_wgh, 2 * D_DIM, g_gpre, D_DIM, 2 * D_DIM,
                              r * 64, c * 128);
            }
        }
        gsync(target);

        // ---------- phase 4: gate + fuse + residual + LayerNorm (row per warp) ----------
        {
            const int lane = tid & 31;
            const int gw = blockIdx.x * 8 + (tid >> 5);
            const int nw = gridDim.x * 8;
            const float* zsn = zs[ncur];
            for (int b = gw; b < B; b += nw) {
                const size_t rb = (size_t)b * D_DIM;
                float f[16];
                float sum = 0.0f;
#pragma unroll
                for (int p = 0; p < 4; p++) {
                    const int j = p * 128 + lane * 4;
                    float4 pr = *(const float4*)(g_gpre + rb + j);
                    float4 gb = *(const float4*)(gateb + j);
                    float4 a  = *(const float4*)(g_zfn + rb + j);
                    float4 s  = *(const float4*)(zsn + rb + j);
                    float4 ho = *(const float4*)(g_zf + rb + j);
                    float g0 = sigm(pr.x + gb.x); f[p*4+0] = s.x + g0 * (a.x - s.x) + ho.x;
                    float g1 = sigm(pr.y + gb.y); f[p*4+1] = s.y + g1 * (a.y - s.y) + ho.y;
                    float g2 = sigm(pr.z + gb.z); f[p*4+2] = s.z + g2 * (a.z - s.z) + ho.z;
                    float g3 = sigm(pr.w + gb.w); f[p*4+3] = s.w + g3 * (a.w - s.w) + ho.w;
                    sum += f[p*4+0] + f[p*4+1] + f[p*4+2] + f[p*4+3];
                }
#pragma unroll
                for (int o = 16; o > 0; o >>= 1) sum += __shfl_xor_sync(0xffffffffu, sum, o);
                const float mu = sum * (1.0f / D_DIM);
                float sq = 0.0f;
#pragma unroll
                for (int k = 0; k < 16; k++) { float d = f[k] - mu; sq += d * d; }
#pragma unroll
                for (int o = 16; o > 0; o >>= 1) sq += __shfl_xor_sync(0xffffffffu, sq, o);
                const float rstd = rsqrtf(sq * (1.0f / D_DIM) + 1e-5f);
#pragma unroll
                for (int p = 0; p < 4; p++) {
                    const int j = p * 128 + lane * 4;
                    float4 gm = *(const float4*)(gamma + j);
                    float4 bt = *(const float4*)(beta + j);
                    float4 y;
                    y.x = (f[p*4+0] - mu) * rstd * gm.x + bt.x;
                    y.y = (f[p*4+1] - mu) * rstd * gm.y + bt.y;
                    y.z = (f[p*4+2] - mu) * rstd * gm.z + bt.z;
                    y.w = (f[p*4+3] - mu) * rstd * gm.w + bt.w;
                    *(float4*)(out + ((size_t)b * T + t) * D_DIM + j) = y;
                    *(float4*)(g_zf + rb + j) = y;
                    *(__half2*)(g_zfh + rb + j)     = make_half2(__float2half_rn(y.x), __float2half_rn(y.y));
                    *(__half2*)(g_zfh + rb + j + 2) = make_half2(__float2half_rn(y.z), __float2half_rn(y.w));
                }
            }
        }
        gsync(target);

        cur = ncur;
    }
}

// ---------------- fused prologue ----------------
// y=0: fast_w_hh->half, y=1: slow_w_hh->half, y=2: gate_w->half,
// y=3: state init (+ barrier reset), y=4: gi fast, y=5: gi slow
__global__ void prep(const float* __restrict__ z_init,
                     const float* __restrict__ emb,
                     const float* __restrict__ fwih, const float* __restrict__ fbih,
                     const float* __restrict__ swih, const float* __restrict__ sbih,
                     const float* __restrict__ fwhh, const float* __restrict__ swhh,
                     const float* __restrict__ gatew,
                     int B, int T)
{
    const int y = blockIdx.y;
    const int tid = threadIdx.x;
    const int BD = B * D_DIM;

    if (y < 3) {
        const float* src = (y == 0) ? fwhh : (y == 1) ? swhh : gatew;
        __half* dst = (y == 0) ? g_wfh : (y == 1) ? g_wsh : g_wgh;
        const int n = (y == 2) ? (D_DIM * 2 * D_DIM) : (3 * D_DIM * D_DIM);
        for (int i = (blockIdx.x * 256 + tid) * 4; i < n; i += gridDim.x * 256 * 4) {
            float4 v = *(const float4*)(src + i);
            *(__half2*)(dst + i)     = make_half2(__float2half_rn(v.x), __float2half_rn(v.y));
            *(__half2*)(dst + i + 2) = make_half2(__float2half_rn(v.z), __float2half_rn(v.w));
        }
    } else if (y == 3) {
        if (blockIdx.x == 0 && tid == 0) g_bar = 0ULL;
        for (int i = (blockIdx.x * 256 + tid) * 4; i < BD; i += gridDim.x * 256 * 4) {
            float4 v = *(const float4*)(z_init + i);
            *(float4*)(g_zf + i)  = v;
            *(float4*)(g_zs0 + i) = v;
            __half2 h01 = make_half2(__float2half_rn(v.x), __float2half_rn(v.y));
            __half2 h23 = make_half2(__float2half_rn(v.z), __float2half_rn(v.w));
            *(__half2*)(g_zfh + i)      = h01;
            *(__half2*)(g_zfh + i + 2)  = h23;
            *(__half2*)(g_zs0h + i)     = h01;
            *(__half2*)(g_zs0h + i + 2) = h23;
        }
    } else {
        const int m = blockIdx.x;            // 0..1535
        if (m >= 3 * D_DIM || tid >= T) return;
        const float* wih = (y == 4) ? fwih : swih;
        const float* bih = (y == 4) ? fbih : sbih;
        float* gi = (y == 4) ? g_gif : g_gis;
        const float4* wr = (const float4*)(wih + (size_t)m * D_DIM);
        const float4* er = (const float4*)(emb + (size_t)tid * D_DIM);
        float s = 0.0f;
        for (int k = 0; k < D_DIM / 4; k++) {
            float4 w = wr[k], e = er[k];
            s += w.x * e.x + w.y * e.y + w.z * e.z + w.w * e.w;
        }
        gi[(size_t)tid * (3 * D_DIM) + m] = s + bih[m];
    }
}

// ---------------- host driver ----------------
extern "C" void kernel_launch(void* const* d_in, const int* in_sizes, int n_in,
                              void* d_out, int out_size)
{
    const float* z_init      = (const float*)d_in[0];
    const float* step_embeds = (const float*)d_in[1];
    const float* fast_w_ih   = (const float*)d_in[2];
    const float* fast_w_hh   = (const float*)d_in[3];
    const float* fast_b_ih   = (const float*)d_in[4];
    const float* fast_b_hh   = (const float*)d_in[5];
    const float* slow_w_ih   = (const float*)d_in[6];
    const float* slow_w_hh   = (const float*)d_in[7];
    const float* slow_b_ih   = (const float*)d_in[8];
    const float* slow_b_hh   = (const float*)d_in[9];
    const float* gate_w      = (const float*)d_in[10];
    const float* gate_b      = (const float*)d_in[11];
    const float* ln_gamma    = (const float*)d_in[12];
    const float* ln_beta     = (const float*)d_in[13];
    float* out = (float*)d_out;

    const int B  = in_sizes[0] / D_DIM;
    const int T  = out_size / (B * D_DIM);

    const int SMEM = SMEM_HALVES * 2;    // 73728 bytes
    static int ncta = 0;
    cudaFuncSetAttribute(fused_scan, cudaFuncAttributeMaxDynamicSharedMemorySize, SMEM);
    if (ncta == 0) {
        int dev = 0, sms = 0, occ = 0;
        cudaGetDevice(&dev);
        cudaDeviceGetAttribute(&sms, cudaDevAttrMultiProcessorCount, dev);
        cudaOccupancyMaxActiveBlocksPerMultiprocessor(&occ, fused_scan, 256, SMEM);
        if (occ < 1) occ = 1;
        if (occ > 2) occ = 2;
        if (sms < 1) sms = 1;
        ncta = sms * occ;
    }

    // prologue: one fused kernel (also resets the grid barrier)
    prep<<<dim3(3 * D_DIM, 6), 256>>>(z_init, step_embeds,
                                      fast_w_ih, fast_b_ih, slow_w_ih, slow_b_ih,
                                      fast_w_hh, slow_w_hh, gate_w, B, T);

    // whole scan in one persistent kernel
    fused_scan<<<ncta, 256, SMEM>>>(fast_b_hh, slow_b_hh, gate_b,
                                    ln_gamma, ln_beta, out, B, T);
}

// round 8
// speedup vs baseline: 1.2867x; 1.2867x over previous
#include <cuda_runtime.h>
#include <cuda_fp16.h>
#include <cstdint>

#define D_DIM 512
#define B_MAX 2048
#define T_CAP 64

// ---------------- device scratch ----------------
__device__ __half g_wfh[3 * D_DIM * D_DIM];
__device__ __half g_wsh[3 * D_DIM * D_DIM];
__device__ __half g_wgh[D_DIM * 2 * D_DIM];
__device__ float  g_gif[T_CAP * 3 * D_DIM];
__device__ float  g_gis[T_CAP * 3 * D_DIM];
__device__ float  g_zf  [B_MAX * D_DIM];
__device__ __half g_zfh [B_MAX * D_DIM];
__device__ float  g_zfn [B_MAX * D_DIM];
__device__ __half g_zfnh[B_MAX * D_DIM];
__device__ float  g_zs0 [B_MAX * D_DIM];
__device__ __half g_zs0h[B_MAX * D_DIM];
__device__ float  g_zs1 [B_MAX * D_DIM];
__device__ __half g_zs1h[B_MAX * D_DIM];
__device__ float  g_ghf[B_MAX * 3 * D_DIM];
__device__ float  g_ghs[B_MAX * 3 * D_DIM];
__device__ float  g_gpre[B_MAX * D_DIM];

// ---------------- helpers ----------------
__device__ __forceinline__ float sigm(float x) { return 1.0f / (1.0f + __expf(-x)); }

__device__ __forceinline__ void mma16(float* c, const uint32_t* a, uint32_t b0, uint32_t b1) {
    asm volatile(
        "mma.sync.aligned.m16n8k16.row.col.f32.f16.f16.f32 "
        "{%0,%1,%2,%3}, {%4,%5,%6,%7}, {%8,%9}, {%0,%1,%2,%3};\n"
        : "+f"(c[0]), "+f"(c[1]), "+f"(c[2]), "+f"(c[3])
        : "r"(a[0]), "r"(a[1]), "r"(a[2]), "r"(a[3]), "r"(b0), "r"(b1));
}

__device__ __forceinline__ void cp16(void* s, const void* g) {
    uint32_t sa = (uint32_t)__cvta_generic_to_shared(s);
    asm volatile("cp.async.cg.shared.global [%0], [%1], 16;\n" :: "r"(sa), "l"(g));
}

__device__ __forceinline__ void ldsm_x4(uint32_t& r0, uint32_t& r1, uint32_t& r2, uint32_t& r3,
                                        uint32_t addr) {
    asm volatile("ldmatrix.sync.aligned.m8n8.x4.shared.b16 {%0,%1,%2,%3}, [%4];"
                 : "=r"(r0), "=r"(r1), "=r"(r2), "=r"(r3) : "r"(addr));
}

// ---------------- fp16 GEMM core: C[tile] = A @ W^T, fp32 accum ----------------
// ldmatrix fragment loads; B-fragments consumed immediately (low reg pressure).
// SSTRH=72 halves (144 B rows): 16B-aligned, conflict-free LDSM phases.
#define KC  64
#define SSTRH 72

template<int TM_, int TN_>
__device__ __forceinline__ void gemm_core(
    __half* hsm,
    const __half* __restrict__ A0, const __half* __restrict__ A1, int splitK, int lda,
    const __half* __restrict__ W, int ldw,
    float* __restrict__ C, int ldc, int K, int rowBase, int colBase)
{
    constexpr int A_STAGE = TM_ * SSTRH;
    constexpr int B_STAGE = TN_ * SSTRH;
    __half* As = hsm;
    __half* Bs = hsm + 2 * A_STAGE;
    const uint32_t a_u32 = (uint32_t)__cvta_generic_to_shared(As);
    const uint32_t b_u32 = (uint32_t)__cvta_generic_to_shared(Bs);

    const int tid = threadIdx.x, warp = tid >> 5, lane = tid & 31;
    constexpr int MW = (TM_ == 128) ? 4 : 2;        // warps along m
    constexpr int NJ = TN_ * MW / 64;               // n8-tiles per warp
    const int wm0 = (warp % MW) * 32;
    const int wn0 = (warp / MW) * (NJ * 8);
    const int group = lane >> 2, tid4 = lane & 3;

    // ldmatrix per-lane base byte offsets (at k=0)
    const int arow = lane & 15, akofs = (lane >> 4) * 8;
    const uint32_t aoff0 = a_u32 + (uint32_t)(((wm0 + arow) * SSTRH + akofs) * 2);
    const uint32_t aoff1 = aoff0 + (uint32_t)(16 * SSTRH * 2);
    const int bw = (lane & 7) + ((lane >> 4) & 1) * 8;
    const int bk = ((lane >> 3) & 1) * 8;
    const uint32_t boff0 = b_u32 + (uint32_t)(((wn0 + bw) * SSTRH + bk) * 2);

    float acc[2][NJ][4];
#pragma unroll
    for (int i = 0; i < 2; i++)
#pragma unroll
        for (int j = 0; j < NJ; j++)
#pragma unroll
            for (int k = 0; k < 4; k++) acc[i][j][k] = 0.0f;

    auto issue = [&](int ic, int buf) {
        const int kk = ic * KC;
        const __half* Ab; int kloc;
        if (kk < splitK) { Ab = A0; kloc = kk; }
        else             { Ab = A1; kloc = kk - splitK; }
        __half* as = As + buf * A_STAGE;
        __half* bs = Bs + buf * B_STAGE;
#pragma unroll
        for (int t = 0; t < TM_ / 32; t++) {
            const int seg = tid + t * 256;
            const int r = seg >> 3, c = (seg & 7) * 8;
            cp16(as + r * SSTRH + c, Ab + (size_t)(rowBase + r) * lda + kloc + c);
        }
#pragma unroll
        for (int t = 0; t < TN_ / 32; t++) {
            const int seg = tid + t * 256;
            const int r = seg >> 3, c = (seg & 7) * 8;
            cp16(bs + r * SSTRH + c, W + (size_t)(colBase + r) * ldw + kk + c);
        }
        asm volatile("cp.async.commit_group;\n" ::);
    };

    const int NK = K / KC;
    issue(0, 0);

    for (int ic = 0; ic < NK; ic++) {
        const int buf = ic & 1;
        if (ic + 1 < NK) {
            issue(ic + 1, buf ^ 1);
            asm volatile("cp.async.wait_group 1;\n" ::);
        } else {
            asm volatile("cp.async.wait_group 0;\n" ::);
        }
        __syncthreads();

        const uint32_t abuf = (uint32_t)(buf * A_STAGE * 2);
        const uint32_t bbuf = (uint32_t)(buf * B_STAGE * 2);
#pragma unroll
        for (int k16 = 0; k16 < KC / 16; k16++) {
            const uint32_t kb = (uint32_t)(k16 * 32);   // k offset in bytes
            uint32_t a[2][4];
            ldsm_x4(a[0][0], a[0][1], a[0][2], a[0][3], aoff0 + abuf + kb);
            ldsm_x4(a[1][0], a[1][1], a[1][2], a[1][3], aoff1 + abuf + kb);
#pragma unroll
            for (int jj = 0; jj < NJ / 2; jj++) {
                uint32_t b00, b01, b10, b11;
                ldsm_x4(b00, b01, b10, b11,
                        boff0 + bbuf + kb + (uint32_t)(jj * 16 * SSTRH * 2));
                mma16(acc[0][2 * jj],     a[0], b00, b01);
                mma16(acc[1][2 * jj],     a[1], b00, b01);
                mma16(acc[0][2 * jj + 1], a[0], b10, b11);
                mma16(acc[1][2 * jj + 1], a[1], b10, b11);
            }
        }
        __syncthreads();
    }

#pragma unroll
    for (int i = 0; i < 2; i++) {
        const int r0 = rowBase + wm0 + i * 16 + group;
#pragma unroll
        for (int j = 0; j < NJ; j++) {
            const int c0 = colBase + wn0 + j * 8 + tid4 * 2;
            *(float2*)&C[(size_t)r0 * ldc + c0]       = make_float2(acc[i][j][0], acc[i][j][1]);
            *(float2*)&C[(size_t)(r0 + 8) * ldc + c0] = make_float2(acc[i][j][2], acc[i][j][3]);
        }
    }
}

// hidden GEMMs: y<12 -> fast tiles; y>=12 -> slow tiles at column (y-12+sbase)
#define HID_SMEM ((2 * 128 + 2 * 128) * SSTRH * 2)
__global__ __launch_bounds__(256, 2) void hidden_gemm(
    const __half* __restrict__ zfh, const __half* __restrict__ zsh, int sbase)
{
    extern __shared__ __half hsm[];
    const int y = blockIdx.y;
    const bool fast = (y < 12);
    const __half* A = fast ? zfh : zsh;
    const __half* W = fast ? g_wfh : g_wsh;
    float*       C  = fast ? g_ghf : g_ghs;
    const int col = fast ? y : (y - 12 + sbase);
    gemm_core<128, 128>(hsm, A, A, 1 << 30, D_DIM, W, D_DIM,
                        C, 3 * D_DIM, D_DIM, blockIdx.x * 128, col * 128);
}

// gate GEMM: 64x64 tiles, K=1024 over concat([zfn, zs]) via split-A
#define GATE_SMEM ((2 * 64 + 2 * 64) * SSTRH * 2)
__global__ __launch_bounds__(256, 2) void gate_gemm(
    const __half* __restrict__ zfnh, const __half* __restrict__ zsnh)
{
    extern __shared__ __half hsm[];
    gemm_core<64, 64>(hsm, zfnh, zsnh, D_DIM, D_DIM, g_wgh, 2 * D_DIM,
                      g_gpre, D_DIM, 2 * D_DIM, blockIdx.x * 64, blockIdx.y * 64);
}

// ---------------- GRU elementwise (fast + optional slow via blockIdx.z) ----------------
__global__ void gru_ew2(const float* __restrict__ gif_t, const float* __restrict__ gis_t,
                        const float* __restrict__ fbhh, const float* __restrict__ sbhh,
                        const float* __restrict__ zsc,
                        float* __restrict__ zsn, __half* __restrict__ zsnh, int BD)
{
    const int slow = blockIdx.z;
    const float* gh  = slow ? g_ghs : g_ghf;
    const float* gi  = slow ? gis_t : gif_t;
    const float* bhh = slow ? sbhh : fbhh;
    const float* h   = slow ? zsc : g_zf;
    float*  ho  = slow ? zsn : g_zfn;
    __half* hoh = slow ? zsnh : g_zfnh;

    int i = (blockIdx.x * blockDim.x + threadIdx.x) * 4;
    if (i >= BD) return;
    const int b = i >> 9;
    const int j = i & (D_DIM - 1);
    const size_t base = (size_t)b * (3 * D_DIM) + j;

    float4 gA = *(const float4*)(gh + base);
    float4 gB = *(const float4*)(gh + base + D_DIM);
    float4 gC = *(const float4*)(gh + base + 2 * D_DIM);
    float4 iA = *(const float4*)(gi + j);
    float4 iB = *(const float4*)(gi + j + D_DIM);
    float4 iC = *(const float4*)(gi + j + 2 * D_DIM);
    float4 bA = *(const float4*)(bhh + j);
    float4 bB = *(const float4*)(bhh + j + D_DIM);
    float4 bC = *(const float4*)(bhh + j + 2 * D_DIM);
    float4 hv = *(const float4*)(h + i);

    float4 o;
    { float r = sigm(iA.x + gA.x + bA.x); float z = sigm(iB.x + gB.x + bB.x);
      float n = tanhf(iC.x + r * (gC.x + bC.x)); o.x = n + z * (hv.x - n); }
    { float r = sigm(iA.y + gA.y + bA.y); float z = sigm(iB.y + gB.y + bB.y);
      float n = tanhf(iC.y + r * (gC.y + bC.y)); o.y = n + z * (hv.y - n); }
    { float r = sigm(iA.z + gA.z + bA.z); float z = sigm(iB.z + gB.z + bB.z);
      float n = tanhf(iC.z + r * (gC.z + bC.z)); o.z = n + z * (hv.z - n); }
    { float r = sigm(iA.w + gA.w + bA.w); float z = sigm(iB.w + gB.w + bB.w);
      float n = tanhf(iC.w + r * (gC.w + bC.w)); o.w = n + z * (hv.w - n); }

    *(float4*)(ho + i) = o;
    *(__half2*)(hoh + i)     = make_half2(__float2half_rn(o.x), __float2half_rn(o.y));
    *(__half2*)(hoh + i + 2) = make_half2(__float2half_rn(o.z), __float2half_rn(o.w));
}

// ---------------- gate + fuse + residual + LayerNorm ----------------
__device__ __forceinline__ float block_sum_128(float v, float* red, int tid) {
#pragma unroll
    for (int o = 16; o > 0; o >>= 1) v += __shfl_xor_sync(0xffffffffu, v, o);
    if ((tid & 31) == 0) red[tid >> 5] = v;
    __syncthreads();
    v = red[0] + red[1] + red[2] + red[3];
    __syncthreads();
    return v;
}

__global__ void gate_fuse_ln(const float* __restrict__ gateb,
                             const float* __restrict__ zs,
                             const float* __restrict__ gamma, const float* __restrict__ beta,
                             float* __restrict__ out, int t, int T)
{
    __shared__ float red[4];
    const int b = blockIdx.x, tid = threadIdx.x;
    const int j = tid * 4;
    const size_t base = (size_t)b * D_DIM + j;

    float4 p  = *(const float4*)(g_gpre + base);
    float4 gb = *(const float4*)(gateb + j);
    float4 a  = *(const float4*)(g_zfn + base);
    float4 s  = *(const float4*)(zs + base);
    float4 ho = *(const float4*)(g_zf + base);

    float f[4];
    { float g = sigm(p.x + gb.x); f[0] = s.x + g * (a.x - s.x) + ho.x; }
    { float g = sigm(p.y + gb.y); f[1] = s.y + g * (a.y - s.y) + ho.y; }
    { float g = sigm(p.z + gb.z); f[2] = s.z + g * (a.z - s.z) + ho.z; }
    { float g = sigm(p.w + gb.w); f[3] = s.w + g * (a.w - s.w) + ho.w; }

    float sum = f[0] + f[1] + f[2] + f[3];
    sum = block_sum_128(sum, red, tid);
    const float mu = sum * (1.0f / D_DIM);

    float sq = 0.0f;
#pragma unroll
    for (int k = 0; k < 4; k++) { float d = f[k] - mu; sq += d * d; }
    sq = block_sum_128(sq, red, tid);
    const float rstd = rsqrtf(sq * (1.0f / D_DIM) + 1e-5f);

    float4 gm = *(const float4*)(gamma + j);
    float4 bt = *(const float4*)(beta + j);
    float4 y;
    y.x = (f[0] - mu) * rstd * gm.x + bt.x;
    y.y = (f[1] - mu) * rstd * gm.y + bt.y;
    y.z = (f[2] - mu) * rstd * gm.z + bt.z;
    y.w = (f[3] - mu) * rstd * gm.w + bt.w;

    *(float4*)(out + ((size_t)b * T + t) * D_DIM + j) = y;
    *(float4*)(g_zf + base) = y;
    *(__half2*)(g_zfh + base)     = make_half2(__float2half_rn(y.x), __float2half_rn(y.y));
    *(__half2*)(g_zfh + base + 2) = make_half2(__float2half_rn(y.z), __float2half_rn(y.w));
}

// ---------------- fused prologue ----------------
__global__ void prep(const float* __restrict__ z_init,
                     const float* __restrict__ emb,
                     const float* __restrict__ fwih, const float* __restrict__ fbih,
                     const float* __restrict__ swih, const float* __restrict__ sbih,
                     const float* __restrict__ fwhh, const float* __restrict__ swhh,
                     const float* __restrict__ gatew,
                     int B, int T)
{
    const int y = blockIdx.y;
    const int tid = threadIdx.x;
    const int BD = B * D_DIM;

    if (y < 3) {
        const float* src = (y == 0) ? fwhh : (y == 1) ? swhh : gatew;
        __half* dst = (y == 0) ? g_wfh : (y == 1) ? g_wsh : g_wgh;
        const int n = (y == 2) ? (D_DIM * 2 * D_DIM) : (3 * D_DIM * D_DIM);
        for (int i = (blockIdx.x * 256 + tid) * 4; i < n; i += gridDim.x * 256 * 4) {
            float4 v = *(const float4*)(src + i);
            *(__half2*)(dst + i)     = make_half2(__float2half_rn(v.x), __float2half_rn(v.y));
            *(__half2*)(dst + i + 2) = make_half2(__float2half_rn(v.z), __float2half_rn(v.w));
        }
    } else if (y == 3) {
        for (int i = (blockIdx.x * 256 + tid) * 4; i < BD; i += gridDim.x * 256 * 4) {
            float4 v = *(const float4*)(z_init + i);
            *(float4*)(g_zf + i)  = v;
            *(float4*)(g_zs0 + i) = v;
            __half2 h01 = make_half2(__float2half_rn(v.x), __float2half_rn(v.y));
            __half2 h23 = make_half2(__float2half_rn(v.z), __float2half_rn(v.w));
            *(__half2*)(g_zfh + i)      = h01;
            *(__half2*)(g_zfh + i + 2)  = h23;
            *(__half2*)(g_zs0h + i)     = h01;
            *(__half2*)(g_zs0h + i + 2) = h23;
        }
    } else {
        const int m = blockIdx.x;
        if (m >= 3 * D_DIM || tid >= T) return;
        const float* wih = (y == 4) ? fwih : swih;
        const float* bih = (y == 4) ? fbih : sbih;
        float* gi = (y == 4) ? g_gif : g_gis;
        const float4* wr = (const float4*)(wih + (size_t)m * D_DIM);
        const float4* er = (const float4*)(emb + (size_t)tid * D_DIM);
        float s = 0.0f;
        for (int k = 0; k < D_DIM / 4; k++) {
            float4 w = wr[k], e = er[k];
            s += w.x * e.x + w.y * e.y + w.z * e.z + w.w * e.w;
        }
        gi[(size_t)tid * (3 * D_DIM) + m] = s + bih[m];
    }
}

// ---------------- host driver ----------------
extern "C" void kernel_launch(void* const* d_in, const int* in_sizes, int n_in,
                              void* d_out, int out_size)
{
    const float* z_init      = (const float*)d_in[0];
    const float* step_embeds = (const float*)d_in[1];
    const float* fast_w_ih   = (const float*)d_in[2];
    const float* fast_w_hh   = (const float*)d_in[3];
    const float* fast_b_ih   = (const float*)d_in[4];
    const float* fast_b_hh   = (const float*)d_in[5];
    const float* slow_w_ih   = (const float*)d_in[6];
    const float* slow_w_hh   = (const float*)d_in[7];
    const float* slow_b_ih   = (const float*)d_in[8];
    const float* slow_b_hh   = (const float*)d_in[9];
    const float* gate_w      = (const float*)d_in[10];
    const float* gate_b      = (const float*)d_in[11];
    const float* ln_gamma    = (const float*)d_in[12];
    const float* ln_beta     = (const float*)d_in[13];
    float* out = (float*)d_out;

    const int B  = in_sizes[0] / D_DIM;
    const int T  = out_size / (B * D_DIM);
    const int BD = B * D_DIM;

    // ALL device-symbol pointers via cudaGetSymbolAddress (host shadow is invalid)
    __half *zfh, *zfnh, *zsAh, *zsBh;
    float *gif, *gis, *zsA, *zsB;
    cudaGetSymbolAddress((void**)&zfh,  g_zfh);
    cudaGetSymbolAddress((void**)&gif,  g_gif);
    cudaGetSymbolAddress((void**)&gis,  g_gis);
    cudaGetSymbolAddress((void**)&zfnh, g_zfnh);
    cudaGetSymbolAddress((void**)&zsA,  g_zs0);
    cudaGetSymbolAddress((void**)&zsAh, g_zs0h);
    cudaGetSymbolAddress((void**)&zsB,  g_zs1);
    cudaGetSymbolAddress((void**)&zsBh, g_zs1h);
    float*  zs[2]  = { zsA, zsB };
    __half* zsh[2] = { zsAh, zsBh };

    cudaFuncSetAttribute(hidden_gemm, cudaFuncAttributeMaxDynamicSharedMemorySize, HID_SMEM);
    cudaFuncSetAttribute(gate_gemm,   cudaFuncAttributeMaxDynamicSharedMemorySize, GATE_SMEM);

    // prologue
    prep<<<dim3(3 * D_DIM, 6), 256>>>(z_init, step_embeds,
                                      fast_w_ih, fast_b_ih, slow_w_ih, slow_b_ih,
                                      fast_w_hh, slow_w_hh, gate_w, B, T);

    const int ewBlocks = (BD / 4 + 255) / 256;
    const int MT = B / 128;

    int cur = 0;
    for (int t = 0; t < T; t++) {
        const bool even = ((t & 1) == 0);

        // hidden GEMMs: fast (12 cols) + slow tile slice (balanced across steps)
        // t==0: full slow (12). odd t: first half of NEXT even step's slow (6).
        // even t>=2: second half of this step's slow (6).
        int nslow, sbase;
        if (t == 0)      { nslow = 12; sbase = 0; }
        else if (!even)  { nslow = (t + 1 < T) ? 6 : 0; sbase = 0; }
        else             { nslow = 6;  sbase = 6; }

        {
            dim3 grid(MT, 12 + nslow, 1);
            hidden_gemm<<<grid, 256, HID_SMEM>>>(zfh, zsh[cur], sbase);
        }

        // GRU elementwise (fast + slow on even steps)
        const int ncur = even ? (cur ^ 1) : cur;
        {
            dim3 grid(ewBlocks, 1, even ? 2 : 1);
            gru_ew2<<<grid, 256>>>(gif + (size_t)t * 3 * D_DIM, gis + (size_t)t * 3 * D_DIM,
                                   fast_b_hh, slow_b_hh,
                                   zs[cur], zs[ncur], zsh[ncur], BD);
        }

        // gate GEMM: 64x64 tiles, 32x8 grid
        {
            dim3 grid(B / 64, D_DIM / 64, 1);
            gate_gemm<<<grid, 256, GATE_SMEM>>>(zfnh, zsh[ncur]);
        }

        // fuse + residual + LN
        gate_fuse_ln<<<B, 128>>>(gate_b, zs[ncur], ln_gamma, ln_beta, out, t, T);

        cur = ncur;
    }
}